// round 1
// baseline (speedup 1.0000x reference)
#include <cuda_runtime.h>
#include <cstdint>

// SpikeFP64ExtractLow6: per row of 64 {0,1} floats,
//   e = int from x[1..11] (x[1] MSB), s = (e + 1025) & 2047  (= e - 1023 mod 2048)
//   M = 0b1 m0 m1 m2 m3 m4 m5 with m_i = x[12+i]
//   v = (s <= 5) ? (M >> (6 - s)) & 63 : 0
//   out[row][j] = bit (5-j) of v, as float.

__global__ void spike_extract_kernel(const float* __restrict__ x,
                                     float* __restrict__ out,
                                     int n) {
    int row = blockIdx.x * blockDim.x + threadIdx.x;
    if (row >= n) return;

    const float4* p = reinterpret_cast<const float4*>(x + (size_t)row * 64);
    // floats 0..19 cover needed indices 1..17; only DRAM sectors 0..2 touched.
    float4 q0 = p[0];
    float4 q1 = p[1];
    float4 q2 = p[2];
    float4 q3 = p[3];
    float4 q4 = p[4];

    float f[20];
    f[0]=q0.x; f[1]=q0.y; f[2]=q0.z; f[3]=q0.w;
    f[4]=q1.x; f[5]=q1.y; f[6]=q1.z; f[7]=q1.w;
    f[8]=q2.x; f[9]=q2.y; f[10]=q2.z; f[11]=q2.w;
    f[12]=q3.x; f[13]=q3.y; f[14]=q3.z; f[15]=q3.w;
    f[16]=q4.x; f[17]=q4.y; f[18]=q4.z; f[19]=q4.w;

    // exponent: x[1] is bit 10 ... x[11] is bit 0
    unsigned e = 0;
    #pragma unroll
    for (int k = 1; k <= 11; k++) {
        e = (e << 1) | (f[k] != 0.0f ? 1u : 0u);
    }
    unsigned s = (e + 1025u) & 2047u;

    // M = implicit 1 followed by 6 mantissa bits (x[12] right after the leading 1)
    unsigned M = 1u;
    #pragma unroll
    for (int i = 0; i < 6; i++) {
        M = (M << 1) | (f[12 + i] != 0.0f ? 1u : 0u);
    }

    unsigned v = (s <= 5u) ? ((M >> (6u - s)) & 63u) : 0u;

    // out row start: row*6 floats = row*24 bytes, 8-byte aligned -> three float2 stores
    float2* o = reinterpret_cast<float2*>(out + (size_t)row * 6);
    float2 w0, w1, w2;
    w0.x = (float)((v >> 5) & 1u);
    w0.y = (float)((v >> 4) & 1u);
    w1.x = (float)((v >> 3) & 1u);
    w1.y = (float)((v >> 2) & 1u);
    w2.x = (float)((v >> 1) & 1u);
    w2.y = (float)(v & 1u);
    o[0] = w0;
    o[1] = w1;
    o[2] = w2;
}

extern "C" void kernel_launch(void* const* d_in, const int* in_sizes, int n_in,
                              void* d_out, int out_size) {
    const float* x = (const float*)d_in[0];
    float* out = (float*)d_out;
    int n = in_sizes[0] / 64;   // 2,000,000 rows
    const int block = 256;
    int grid = (n + block - 1) / block;
    spike_extract_kernel<<<grid, block>>>(x, out, n);
}

// round 3
// speedup vs baseline: 1.0045x; 1.0045x over previous
#include <cuda_runtime.h>
#include <cstdint>

// SpikeFP64ExtractLow6 — warp-ballot formulation, no smem, no __syncthreads.
// Per row of 64 {0,1} floats:
//   e = int from x[1..11] (x[1] MSB), s = (e + 1025) & 2047
//   M = 0b1 m0..m5 with m_i = x[12+i]
//   v = (s <= 5) ? (M >> (6 - s)) & 63 : 0
//   out[row][j] = bit (5-j) of v, as float.
//
// One warp processes 32 consecutive rows. Lane l loads x[row*64 + l] (l<24):
// one 128B line per row -> 1 L1 wavefront/row, sectors 0..2 only (96B DRAM).
// __ballot_sync collects the row's bits into one register; __brev + shifts
// replace the whole soft-adder network. Output written as coalesced STG.128.

__device__ __forceinline__ unsigned decode_v(unsigned rowmask) {
    unsigned rb = __brev(rowmask);
    unsigned e  = (rb >> 20) & 0x7FFu;         // x[1]=MSB ... x[11]=LSB
    unsigned s  = (e + 1025u) & 2047u;         // e - 1023 mod 2048
    unsigned M  = 64u | ((rb >> 14) & 63u);    // 1 m0 m1 m2 m3 m4 m5
    return (s <= 5u) ? ((M >> (6u - s)) & 63u) : 0u;
}

__global__ __launch_bounds__(256) void spike_extract_kernel(
        const float* __restrict__ x,
        float* __restrict__ out,
        int n) {
    const int warpId = (blockIdx.x * blockDim.x + threadIdx.x) >> 5;
    const int lane   = threadIdx.x & 31;
    const int row0   = warpId * 32;
    if (row0 >= n) return;                      // whole-warp exit only

    if (row0 + 32 <= n) {
        // ---- fast path: 32 full rows per warp ----
        const float* base = x + (size_t)row0 * 64 + lane;
        float vals[32];
        #pragma unroll
        for (int i = 0; i < 32; i++)
            vals[i] = (lane < 24) ? base[(size_t)i * 64] : 0.0f;

        unsigned myb = 0;
        #pragma unroll
        for (int i = 0; i < 32; i++) {
            unsigned b = __ballot_sync(0xFFFFFFFFu, vals[i] != 0.0f);
            if (lane == i) myb = b;
        }

        const unsigned v = decode_v(myb);       // lane l holds v for row row0+l

        // ---- coalesced store: 192 floats = 48 float4 ----
        float4* obase = reinterpret_cast<float4*>(out + (size_t)row0 * 6);

        // round A: float4 index = lane (floats 0..127)
        {
            float4 o;
            #pragma unroll
            for (int j = 0; j < 4; j++) {
                int f  = lane * 4 + j;          // 0..127
                int sr = f / 6;                 // source row lane 0..21
                int bp = 5 - (f - sr * 6);
                unsigned vv = __shfl_sync(0xFFFFFFFFu, v, sr);
                (&o.x)[j] = (float)((vv >> bp) & 1u);
            }
            obase[lane] = o;
        }
        // round B: float4 index = 32 + lane, lanes 0..15 (floats 128..191)
        {
            float4 o;
            #pragma unroll
            for (int j = 0; j < 4; j++) {
                int f  = 128 + lane * 4 + j;    // up to 255 for high lanes
                int sr = f / 6;
                int bp = 5 - (f - sr * 6);
                int src = sr < 32 ? sr : 31;    // clamp; high lanes' data unused
                unsigned vv = __shfl_sync(0xFFFFFFFFu, v, src);
                (&o.x)[j] = (float)((vv >> bp) & 1u);
            }
            if (lane < 16) obase[32 + lane] = o;
        }
    } else {
        // ---- tail path: scalar per-lane (n % 32 rows; never hit for n=2e6) ----
        int row = row0 + lane;
        if (row < n) {
            const float* f = x + (size_t)row * 64;
            unsigned mask = 0;
            #pragma unroll
            for (int k = 1; k <= 17; k++)
                mask |= (f[k] != 0.0f ? 1u : 0u) << k;
            unsigned v = decode_v(mask);
            float* o = out + (size_t)row * 6;
            #pragma unroll
            for (int j = 0; j < 6; j++)
                o[j] = (float)((v >> (5 - j)) & 1u);
        }
    }
}

extern "C" void kernel_launch(void* const* d_in, const int* in_sizes, int n_in,
                              void* d_out, int out_size) {
    const float* x = (const float*)d_in[0];
    float* out = (float*)d_out;
    int n = in_sizes[0] / 64;                 // 2,000,000 rows
    int nwarps = (n + 31) / 32;
    int nthreads = nwarps * 32;
    int grid = (nthreads + 255) / 256;
    spike_extract_kernel<<<grid, 256>>>(x, out, n);
}